// round 15
// baseline (speedup 1.0000x reference)
#include <cuda_runtime.h>
#include <cuda_fp16.h>
#include <cstdint>
#include <math.h>

using u32 = unsigned int;

// Problem constants
#define BB 4
#define TT 2048
#define DD 2048
#define HH 16
#define HDIM 128

// Scratch (allocation-free rule: __device__ globals)
__device__ float g_y[(size_t)BB * TT * DD];         // (B*T, D)
__device__ float g_xr[(size_t)BB * TT * DD];        // tf32-rounded x
__device__ float g_wq[(size_t)3 * DD * DD];         // tf32-rounded w_qkv
__device__ float g_wo[(size_t)DD * DD];             // tf32-rounded w_o
// fp16 Q/K/V planes: [(b*16+h)][t][128] half (row = 256B), as u32
__device__ u32 g_qh[(size_t)64 * 2048 * 64];
__device__ u32 g_ql[(size_t)64 * 2048 * 64];
__device__ u32 g_kh[(size_t)64 * 2048 * 64];
__device__ u32 g_kl[(size_t)64 * 2048 * 64];
__device__ u32 g_vh[(size_t)64 * 2048 * 64];

__device__ __forceinline__ u32 smem_u32(const void* p) {
    u32 a;
    asm("{ .reg .u64 t; cvta.to.shared.u64 t, %1; cvt.u32.u64 %0, t; }"
        : "=r"(a) : "l"(p));
    return a;
}

__device__ __forceinline__ u32 f2tf32(float f) {
    u32 u;
    asm("cvt.rna.tf32.f32 %0, %1;" : "=r"(u) : "f"(f));
    return u;
}

// pack two fp32 into f16x2 (first arg in low half)
__device__ __forceinline__ u32 packf16(float lo, float hi) {
    u32 r;
    asm("cvt.rn.f16x2.f32 %0, %1, %2;" : "=r"(r) : "f"(hi), "f"(lo));
    return r;
}

__device__ __forceinline__ void hsplit(float v, float& hi, float& lo) {
    __half h = __float2half_rn(v);
    hi = __half2float(h);
    lo = v - hi;
}

__device__ __forceinline__ void pack_hsplit2(float a, float b, u32& hp, u32& lp) {
    float ha, la, hb, lb;
    hsplit(a, ha, la);
    hsplit(b, hb, lb);
    hp = packf16(ha, hb);
    lp = packf16(la, lb);
}

// ---------------------------------------------------------------------------
// Pre-round pass: dst[i] = tf32_rna(src[i])
// ---------------------------------------------------------------------------
__global__ void round_tf32(const float* __restrict__ src, float* __restrict__ dst,
                           int n4) {
    int i = blockIdx.x * blockDim.x + threadIdx.x;
    if (i < n4) {
        float4 v = ((const float4*)src)[i];
        ((float4*)dst)[i] = make_float4(
            __uint_as_float(f2tf32(v.x)), __uint_as_float(f2tf32(v.y)),
            __uint_as_float(f2tf32(v.z)), __uint_as_float(f2tf32(v.w)));
    }
}

// ---------------------------------------------------------------------------
// TF32 GEMM (R10 core, known-pass) + fused Q/K/V fp16-split epilogue.
// qkv_mode: Q section -> qh/ql, K -> kh/kl, V -> vh. No fp32 C writes.
// ---------------------------------------------------------------------------
#define GST 36
#define A_BYTES (128 * GST * 4)
#define STAGE_B (2 * A_BYTES)
#define GEMM_SMEM3 (3 * STAGE_B)
#define RCHUNK (32 * GST * 4)

__device__ __forceinline__ void mma_tf32(float* d, const u32* a, const u32* b) {
    asm volatile(
        "mma.sync.aligned.m16n8k8.row.col.f32.tf32.tf32.f32 "
        "{%0,%1,%2,%3}, {%4,%5,%6,%7}, {%8,%9}, {%0,%1,%2,%3};"
        : "+f"(d[0]), "+f"(d[1]), "+f"(d[2]), "+f"(d[3])
        : "r"(a[0]), "r"(a[1]), "r"(a[2]), "r"(a[3]), "r"(b[0]), "r"(b[1]));
}

__device__ __forceinline__ void ldmx4(u32* r, u32 addr) {
    asm volatile("ldmatrix.sync.aligned.m8n8.x4.shared.b16 {%0,%1,%2,%3}, [%4];"
                 : "=r"(r[0]), "=r"(r[1]), "=r"(r[2]), "=r"(r[3]) : "r"(addr));
}

__device__ __forceinline__ void cp16(u32 dst, const void* src) {
    asm volatile("cp.async.cg.shared.global [%0], [%1], 16;"
                 :: "r"(dst), "l"(src) : "memory");
}

__global__ __launch_bounds__(256, 2)
void gemm_nt_tf32p(const float* __restrict__ A, const float* __restrict__ B,
                   float* __restrict__ C, int M, int N, int K,
                   u32* __restrict__ qh, u32* __restrict__ ql,
                   u32* __restrict__ kh, u32* __restrict__ kl,
                   u32* __restrict__ vh, int qkv_mode) {
    extern __shared__ char sm3[];
    const u32 sbase = smem_u32(sm3);
    const int tid = threadIdx.x;
    const int warp = tid >> 5, lane = tid & 31;
    const int wm = warp >> 1, wn = warp & 1;
    const int fr = lane >> 2, fc = lane & 3;
    const int row0 = blockIdx.y * 128, col0 = blockIdx.x * 128;

    const int lrow = tid >> 3, lcc = tid & 7;
    const u32 so0 = (u32)(lrow * GST + lcc * 4) * 4;
    const float* ga0 = A + (size_t)(row0 + lrow) * K + lcc * 4;
    const float* gb0 = B + (size_t)(col0 + lrow) * K + lcc * 4;
    const size_t rstep = (size_t)32 * K;

    const int gl = lane >> 3, lr8 = lane & 7;
    const u32 afrag = (u32)((wm * 32 + (gl & 1) * 8 + lr8) * GST + (gl >> 1) * 4) * 4;
    const u32 bfrag = A_BYTES +
        (u32)((wn * 64 + (gl >> 1) * 8 + lr8) * GST + (gl & 1) * 4) * 4;

    float acc[2][8][4];
#pragma unroll
    for (int mf = 0; mf < 2; mf++)
#pragma unroll
        for (int g = 0; g < 8; g++)
#pragma unroll
            for (int i = 0; i < 4; i++) acc[mf][g][i] = 0.f;

    const int nslabs = K / 32;

#define ISSUE(slab)                                                          \
    {                                                                        \
        const int st_ = (slab) % 3;                                          \
        const int k0_ = (slab) * 32;                                         \
        const u32 sb_ = sbase + st_ * STAGE_B;                               \
        _Pragma("unroll")                                                    \
        for (int s_ = 0; s_ < 4; s_++) {                                     \
            cp16(sb_ + so0 + RCHUNK * s_, ga0 + rstep * s_ + k0_);           \
            cp16(sb_ + A_BYTES + so0 + RCHUNK * s_, gb0 + rstep * s_ + k0_); \
        }                                                                    \
        asm volatile("cp.async.commit_group;" ::: "memory");                 \
    }

    ISSUE(0);
    ISSUE(1);

#pragma unroll 1
    for (int c = 0; c < nslabs; c++) {
        if (c + 1 < nslabs)
            asm volatile("cp.async.wait_group 1;" ::: "memory");
        else
            asm volatile("cp.async.wait_group 0;" ::: "memory");
        __syncthreads();
        if (c + 2 < nslabs) ISSUE(c + 2);

        const u32 sb = sbase + (c % 3) * STAGE_B;
#pragma unroll
        for (int ks = 0; ks < 32; ks += 8) {
            u32 a[2][4], b[8][2];
            ldmx4(a[0], sb + afrag + ks * 4);
            ldmx4(a[1], sb + afrag + 16 * GST * 4 + ks * 4);
#pragma unroll
            for (int j = 0; j < 4; j++) {
                u32 r[4];
                ldmx4(r, sb + bfrag + j * 16 * GST * 4 + ks * 4);
                b[2 * j][0] = r[0]; b[2 * j][1] = r[1];
                b[2 * j + 1][0] = r[2]; b[2 * j + 1][1] = r[3];
            }
#pragma unroll
            for (int mf = 0; mf < 2; mf++)
#pragma unroll
                for (int g = 0; g < 8; g++)
                    mma_tf32(acc[mf][g], a[mf], b[g]);
        }
    }

    // Epilogue
    if (qkv_mode) {
        const int sec = col0 >> 11;                 // 0=Q, 1=K, 2=V
        u32* __restrict__ ph = (sec == 0) ? qh : (sec == 1) ? kh : vh;
        u32* __restrict__ pl = (sec == 0) ? ql : kl;   // unused for V
        const int h = (col0 >> 7) & 15;
#pragma unroll
        for (int mf = 0; mf < 2; mf++) {
#pragma unroll
            for (int g = 0; g < 8; g++) {
                int rr = row0 + wm * 32 + mf * 16 + fr;
                int cc = col0 + wn * 64 + g * 8 + 2 * fc;
                int cu = (cc & 127) >> 1;
#pragma unroll
                for (int half = 0; half < 2; half++) {
                    int r2 = rr + half * 8;
                    int bb = r2 >> 11, tok = r2 & 2047;
                    size_t base = ((size_t)(bb * 16 + h) * 2048 + tok) * 64 + cu;
                    float a0 = acc[mf][g][half * 2], a1 = acc[mf][g][half * 2 + 1];
                    if (sec == 2) {
                        ph[base] = packf16(a0, a1);
                    } else {
                        u32 hp, lp;
                        pack_hsplit2(a0, a1, hp, lp);
                        ph[base] = hp;
                        pl[base] = lp;
                    }
                }
            }
        }
    } else {
#pragma unroll
        for (int mf = 0; mf < 2; mf++) {
#pragma unroll
            for (int g = 0; g < 8; g++) {
                int rr = row0 + wm * 32 + mf * 16 + fr;
                int cc = col0 + wn * 64 + g * 8 + 2 * fc;
                *(float2*)(C + (size_t)rr * N + cc) =
                    make_float2(acc[mf][g][0], acc[mf][g][1]);
                *(float2*)(C + (size_t)(rr + 8) * N + cc) =
                    make_float2(acc[mf][g][2], acc[mf][g][3]);
            }
        }
    }
#undef ISSUE
}

// ===========================================================================
// Flash attention v8: 128 threads, 4 warps x 32 q-rows (2 m-blocks each).
// Q fp16 hi/lo planes resident in smem (loaded once); K/V double-buffered.
// QK: 3-term fp16 split. PV: single fp16 mma. Same mma orders as R14.
// ===========================================================================
#define QPL 32768                      // bytes per Q plane (128 rows x 256B)
#define KSTG_OFF 65536                 // K/V stages start
#define APL 16384                      // bytes per K/V plane per stage
#define ASTAGE (3 * APL)               // 49152
#define ABIAS_OFF (KSTG_OFF + 2 * ASTAGE)   // 163840
#define ATTN_SMEM (ABIAS_OFF + 2048 * 4)    // 172032

__device__ __forceinline__ void mma_f16(float* c, const u32* a, const u32* b) {
    asm volatile(
        "mma.sync.aligned.m16n8k16.row.col.f32.f16.f16.f32 "
        "{%0,%1,%2,%3}, {%4,%5,%6,%7}, {%8,%9}, {%0,%1,%2,%3};"
        : "+f"(c[0]), "+f"(c[1]), "+f"(c[2]), "+f"(c[3])
        : "r"(a[0]), "r"(a[1]), "r"(a[2]), "r"(a[3]), "r"(b[0]), "r"(b[1]));
}

__device__ __forceinline__ void ldsm_x2(u32& r0, u32& r1, u32 addr) {
    asm volatile("ldmatrix.sync.aligned.m8n8.x2.shared.b16 {%0,%1}, [%2];"
                 : "=r"(r0), "=r"(r1) : "r"(addr));
}

__device__ __forceinline__ void ldsm_x2_t(u32& r0, u32& r1, u32 addr) {
    asm volatile("ldmatrix.sync.aligned.m8n8.x2.trans.shared.b16 {%0,%1}, [%2];"
                 : "=r"(r0), "=r"(r1) : "r"(addr));
}

__device__ __forceinline__ float exp2_fast(float t) {
    t = fmaxf(t, -126.f);
    float k = rintf(t);
    float f = t - k;
    float u = f * 0.69314718056f;
    float p = 0.0013888889f;
    p = fmaf(p, u, 0.008333334f);
    p = fmaf(p, u, 0.041666668f);
    p = fmaf(p, u, 0.16666667f);
    p = fmaf(p, u, 0.5f);
    p = fmaf(p, u, 1.0f);
    p = fmaf(p, u, 1.0f);
    return __int_as_float(((int)k + 127) << 23) * p;
}

__global__ __launch_bounds__(128)
void attn_mma(const int* __restrict__ mask,
              const u32* __restrict__ qh, const u32* __restrict__ ql,
              const u32* __restrict__ kh, const u32* __restrict__ kl,
              const u32* __restrict__ vh, float* __restrict__ y) {
    extern __shared__ char smA[];
    const u32 sbase = smem_u32(smA);
    float* biasS = (float*)(smA + ABIAS_OFF);

    const int tid = threadIdx.x;
    const int warp = tid >> 5, lane = tid & 31;
    const int fr = lane >> 2, fc = lane & 3;
    const int qt = blockIdx.x;          // 0..15 (128-row q tiles)
    const int bh = blockIdx.y;          // 0..63
    const int b = bh >> 4, h = bh & 15;

    const float C = 0.12751743f;        // (1/sqrt(128)) * log2(e)

    const size_t pbase = (size_t)bh * 2048 * 256;
    const char* pqh = (const char*)qh + pbase;
    const char* pql = (const char*)ql + pbase;
    const char* pkh = (const char*)kh + pbase;
    const char* pkl = (const char*)kl + pbase;
    const char* pvh = (const char*)vh + pbase;

    // bias table (plain stores; visible after first __syncthreads)
    {
        const int* mg = mask + b * TT;
        for (int t = tid; t < TT; t += 128)
            biasS[t] = mg[t] ? 0.f : -1e30f;
    }

    // ---- Q planes -> smem (once), then first K/V stage; one commit group ----
#pragma unroll
    for (int i = 0; i < 32; i++) {
        int cid = tid + (i & 15) * 128;
        int row = cid >> 4, c = cid & 15;
        const char* p = (i >> 4) ? pql : pqh;
        u32 d = sbase + (u32)(i >> 4) * QPL + row * 256 + (((u32)(c ^ (row & 7))) << 4);
        cp16(d, p + (size_t)(qt * 128 + row) * 256 + c * 16);
    }

#define AISSUE(ktc)                                                            \
    {                                                                          \
        const u32 sb_ = sbase + KSTG_OFF + ((ktc) & 1) * ASTAGE;               \
        const size_t go_ = (size_t)(ktc) * 16384;                              \
        _Pragma("unroll")                                                      \
        for (int i_ = 0; i_ < 24; i_++) {                                      \
            int cid_ = tid + (i_ & 7) * 128;                                   \
            int row_ = cid_ >> 4, c_ = cid_ & 15;                              \
            const char* p_ = (i_ >> 3) == 0 ? pkh                              \
                           : (i_ >> 3) == 1 ? pkl : pvh;                       \
            u32 d_ = sb_ + (u32)(i_ >> 3) * APL + row_ * 256 +                 \
                     (((u32)(c_ ^ (row_ & 7))) << 4);                          \
            cp16(d_, p_ + go_ + row_ * 256 + c_ * 16);                         \
        }                                                                      \
        asm volatile("cp.async.commit_group;" ::: "memory");                   \
    }

    AISSUE(0);   // commits Q + stage0 together

    float o[2][16][4];
#pragma unroll
    for (int blk = 0; blk < 2; blk++)
#pragma unroll
        for (int n = 0; n < 16; n++)
#pragma unroll
            for (int j = 0; j < 4; j++) o[blk][n][j] = 0.f;
    float mS[2][2], lS[2][2];
#pragma unroll
    for (int blk = 0; blk < 2; blk++) {
        mS[blk][0] = -1e30f; mS[blk][1] = -1e30f;
        lS[blk][0] = 0.f;    lS[blk][1] = 0.f;
    }

    const int lr8 = lane & 7;
    const int lh = (lane >> 3) & 1;
    const int lq = (lane >> 4) & 1;
    const int lrow16 = lane & 15;
    const int qrowbase = warp * 32 + lr8 + lh * 8;   // A-frag row (block 0)
    const u32 qbaseoff = (u32)qrowbase * 256;

#define KOFF(kf_, n_) \
    ((u32)(((n_) * 8 + lr8) * 256) + ((u32)(((kf_) * 2 + lh) ^ lr8) << 4))
#define VOFF(n_, kf_) \
    ((u32)(((kf_) * 16 + lrow16) * 256) + ((u32)((n_) ^ (lrow16 & 7)) << 4))

#pragma unroll 1
    for (int kt = 0; kt < TT / 64; kt++) {
        asm volatile("cp.async.wait_group 0;" ::: "memory");
        __syncthreads();
        if (kt + 1 < TT / 64) AISSUE(kt + 1);

        const u32 sb = sbase + KSTG_OFF + (kt & 1) * ASTAGE;

        // ---- S = Q K^T (fp16x3) for both m-blocks ----
        float s[2][8][4];
#pragma unroll
        for (int blk = 0; blk < 2; blk++)
#pragma unroll
            for (int n = 0; n < 8; n++)
#pragma unroll
                for (int j = 0; j < 4; j++) s[blk][n][j] = 0.f;

#pragma unroll
        for (int kf = 0; kf < 8; kf++) {
            // A fragments for this kf: both blocks, hi+lo
            u32 a0h[4], a0l[4], a1h[4], a1l[4];
            u32 sw = ((u32)((kf * 2 + lq) ^ (qrowbase & 7))) << 4;
            ldmx4(a0h, sbase + qbaseoff + sw);
            ldmx4(a0l, sbase + QPL + qbaseoff + sw);
            ldmx4(a1h, sbase + qbaseoff + 4096 + sw);
            ldmx4(a1l, sbase + QPL + qbaseoff + 4096 + sw);

            // B fragments double-buffered over n
            u32 bhf[2][2], blf[2][2];
            u32 off0 = KOFF(kf, 0);
            ldsm_x2(bhf[0][0], bhf[0][1], sb + off0);
            ldsm_x2(blf[0][0], blf[0][1], sb + APL + off0);
#pragma unroll
            for (int n = 0; n < 8; n++) {
                const int cur = n & 1, nxt = cur ^ 1;
                if (n < 7) {
                    u32 off = KOFF(kf, n + 1);
                    ldsm_x2(bhf[nxt][0], bhf[nxt][1], sb + off);
                    ldsm_x2(blf[nxt][0], blf[nxt][1], sb + APL + off);
                }
                mma_f16(s[0][n], a0h, bhf[cur]);
                mma_f16(s[0][n], a0l, bhf[cur]);
                mma_f16(s[0][n], a0h, blf[cur]);
                mma_f16(s[1][n], a1h, bhf[cur]);
                mma_f16(s[1][n], a1l, bhf[cur]);
                mma_f16(s[1][n], a1h, blf[cur]);
            }
        }

        // ---- online softmax (log2 domain), per block ----
        const float* brow = biasS + kt * 64;
        float ff[2][2];
#pragma unroll
        for (int blk = 0; blk < 2; blk++) {
            float mx0 = -1e30f, mx1 = -1e30f;
#pragma unroll
            for (int n = 0; n < 8; n++) {
                float2 bb = *(const float2*)&brow[n * 8 + 2 * fc];
                s[blk][n][0] = fmaf(s[blk][n][0], C, bb.x);
                s[blk][n][1] = fmaf(s[blk][n][1], C, bb.y);
                s[blk][n][2] = fmaf(s[blk][n][2], C, bb.x);
                s[blk][n][3] = fmaf(s[blk][n][3], C, bb.y);
                mx0 = fmaxf(mx0, fmaxf(s[blk][n][0], s[blk][n][1]));
                mx1 = fmaxf(mx1, fmaxf(s[blk][n][2], s[blk][n][3]));
            }
            mx0 = fmaxf(mx0, __shfl_xor_sync(0xffffffffu, mx0, 1));
            mx0 = fmaxf(mx0, __shfl_xor_sync(0xffffffffu, mx0, 2));
            mx1 = fmaxf(mx1, __shfl_xor_sync(0xffffffffu, mx1, 1));
            mx1 = fmaxf(mx1, __shfl_xor_sync(0xffffffffu, mx1, 2));

            float m0n = fmaxf(mS[blk][0], mx0), m1n = fmaxf(mS[blk][1], mx1);
            ff[blk][0] = exp2_fast(mS[blk][0] - m0n);
            ff[blk][1] = exp2_fast(mS[blk][1] - m1n);
            mS[blk][0] = m0n; mS[blk][1] = m1n;

            float sum0 = 0.f, sum1 = 0.f;
#pragma unroll
            for (int n = 0; n < 8; n++) {
                s[blk][n][0] = exp2_fast(s[blk][n][0] - m0n);
                s[blk][n][1] = exp2_fast(s[blk][n][1] - m0n);
                s[blk][n][2] = exp2_fast(s[blk][n][2] - m1n);
                s[blk][n][3] = exp2_fast(s[blk][n][3] - m1n);
                sum0 += s[blk][n][0] + s[blk][n][1];
                sum1 += s[blk][n][2] + s[blk][n][3];
            }
            sum0 += __shfl_xor_sync(0xffffffffu, sum0, 1);
            sum0 += __shfl_xor_sync(0xffffffffu, sum0, 2);
            sum1 += __shfl_xor_sync(0xffffffffu, sum1, 1);
            sum1 += __shfl_xor_sync(0xffffffffu, sum1, 2);
            lS[blk][0] = lS[blk][0] * ff[blk][0] + sum0;
            lS[blk][1] = lS[blk][1] * ff[blk][1] + sum1;

#pragma unroll
            for (int n = 0; n < 16; n++) {
                o[blk][n][0] *= ff[blk][0]; o[blk][n][1] *= ff[blk][0];
                o[blk][n][2] *= ff[blk][1]; o[blk][n][3] *= ff[blk][1];
            }
        }

        // pack P -> fp16 A fragments per block
        u32 pa[2][4][4];
#pragma unroll
        for (int blk = 0; blk < 2; blk++)
#pragma unroll
            for (int kf = 0; kf < 4; kf++) {
                pa[blk][kf][0] = packf16(s[blk][2 * kf][0], s[blk][2 * kf][1]);
                pa[blk][kf][1] = packf16(s[blk][2 * kf][2], s[blk][2 * kf][3]);
                pa[blk][kf][2] = packf16(s[blk][2 * kf + 1][0], s[blk][2 * kf + 1][1]);
                pa[blk][kf][3] = packf16(s[blk][2 * kf + 1][2], s[blk][2 * kf + 1][3]);
            }

        // ---- O += P V (single fp16 mma), V fragments double-buffered ----
        {
            u32 bv[2][2];
            u32 off0 = VOFF(0, 0);
            ldsm_x2_t(bv[0][0], bv[0][1], sb + 2 * APL + off0);
#pragma unroll
            for (int idx = 0; idx < 64; idx++) {
                const int n = idx >> 2, kf = idx & 3;
                const int cur = idx & 1, nxt = cur ^ 1;
                if (idx < 63) {
                    const int i2 = idx + 1;
                    u32 off = VOFF(i2 >> 2, i2 & 3);
                    ldsm_x2_t(bv[nxt][0], bv[nxt][1], sb + 2 * APL + off);
                }
                mma_f16(o[0][n], pa[0][kf], bv[cur]);
                mma_f16(o[1][n], pa[1][kf], bv[cur]);
            }
        }
    }
#undef AISSUE
#undef KOFF
#undef VOFF

    // ---- normalize and store (tf32-rounded) ----
#pragma unroll
    for (int blk = 0; blk < 2; blk++) {
        float inv0 = 1.f / lS[blk][0], inv1 = 1.f / lS[blk][1];
        size_t r0 = (size_t)(b * TT + qt * 128 + warp * 32 + blk * 16 + fr) * DD
                  + h * HDIM;
        size_t r1 = r0 + (size_t)8 * DD;
#pragma unroll
        for (int n = 0; n < 16; n++) {
            int cc = n * 8 + 2 * fc;
            *(float2*)(y + r0 + cc) = make_float2(
                __uint_as_float(f2tf32(o[blk][n][0] * inv0)),
                __uint_as_float(f2tf32(o[blk][n][1] * inv0)));
            *(float2*)(y + r1 + cc) = make_float2(
                __uint_as_float(f2tf32(o[blk][n][2] * inv1)),
                __uint_as_float(f2tf32(o[blk][n][3] * inv1)));
        }
    }
}

// ---------------------------------------------------------------------------
// Launch
// ---------------------------------------------------------------------------
extern "C" void kernel_launch(void* const* d_in, const int* in_sizes, int n_in,
                              void* d_out, int out_size) {
    const float* x     = (const float*)d_in[0];
    const int*   mask  = (const int*)d_in[1];
    const float* w_qkv = (const float*)d_in[2];
    const float* w_o   = (const float*)d_in[3];
    float* out = (float*)d_out;

    float *yb, *xr, *wq, *wo;
    u32 *qh, *ql, *kh, *kl, *vh;
    cudaGetSymbolAddress((void**)&yb, g_y);
    cudaGetSymbolAddress((void**)&xr, g_xr);
    cudaGetSymbolAddress((void**)&wq, g_wq);
    cudaGetSymbolAddress((void**)&wo, g_wo);
    cudaGetSymbolAddress((void**)&qh, g_qh);
    cudaGetSymbolAddress((void**)&ql, g_ql);
    cudaGetSymbolAddress((void**)&kh, g_kh);
    cudaGetSymbolAddress((void**)&kl, g_kl);
    cudaGetSymbolAddress((void**)&vh, g_vh);
    cudaFuncSetAttribute(gemm_nt_tf32p, cudaFuncAttributeMaxDynamicSharedMemorySize,
                         GEMM_SMEM3);
    cudaFuncSetAttribute(attn_mma, cudaFuncAttributeMaxDynamicSharedMemorySize,
                         ATTN_SMEM);

    // Pre-round GEMM inputs to tf32
    {
        int n4x = (BB * TT * DD) / 4;
        int n4q = (3 * DD * DD) / 4;
        int n4o = (DD * DD) / 4;
        round_tf32<<<(n4x + 255) / 256, 256>>>(x, xr, n4x);
        round_tf32<<<(n4q + 255) / 256, 256>>>(w_qkv, wq, n4q);
        round_tf32<<<(n4o + 255) / 256, 256>>>(w_o, wo, n4o);
    }

    // QKV = X @ Wqkv^T, all sections split to fp16 planes in-epilogue
    gemm_nt_tf32p<<<dim3(3 * DD / 128, BB * TT / 128), 256, GEMM_SMEM3>>>(
        xr, wq, nullptr, BB * TT, 3 * DD, DD, qh, ql, kh, kl, vh, 1);

    // Attention -> y (tf32-rounded)
    attn_mma<<<dim3(TT / 128, BB * HH), 128, ATTN_SMEM>>>(
        mask, qh, ql, kh, kl, vh, yb);

    // out = Y @ Wo^T
    gemm_nt_tf32p<<<dim3(DD / 128, BB * TT / 128), 256, GEMM_SMEM3>>>(
        yb, wo, out, BB * TT, DD, DD,
        nullptr, nullptr, nullptr, nullptr, nullptr, 0);
}

// round 16
// speedup vs baseline: 1.2271x; 1.2271x over previous
#include <cuda_runtime.h>
#include <cuda_fp16.h>
#include <cstdint>
#include <math.h>

using u32 = unsigned int;

// Problem constants
#define BB 4
#define TT 2048
#define DD 2048
#define HH 16
#define HDIM 128

// Scratch (allocation-free rule: __device__ globals)
__device__ float g_qkv[(size_t)BB * TT * 3 * DD];   // (B*T, 3D): Q fp32; K/V unused
__device__ float g_y[(size_t)BB * TT * DD];         // (B*T, D)
__device__ float g_xr[(size_t)BB * TT * DD];        // tf32-rounded x
__device__ float g_wq[(size_t)3 * DD * DD];         // tf32-rounded w_qkv
__device__ float g_wo[(size_t)DD * DD];             // tf32-rounded w_o
// fp16 K/V planes: [(b*16+h)][t][128] half (row = 256B), as u32
__device__ u32 g_kh[(size_t)64 * 2048 * 64];
__device__ u32 g_vh[(size_t)64 * 2048 * 64];

__device__ __forceinline__ u32 smem_u32(const void* p) {
    u32 a;
    asm("{ .reg .u64 t; cvta.to.shared.u64 t, %1; cvt.u32.u64 %0, t; }"
        : "=r"(a) : "l"(p));
    return a;
}

__device__ __forceinline__ u32 f2tf32(float f) {
    u32 u;
    asm("cvt.rna.tf32.f32 %0, %1;" : "=r"(u) : "f"(f));
    return u;
}

// pack two fp32 into f16x2 (first arg in low half)
__device__ __forceinline__ u32 packf16(float lo, float hi) {
    u32 r;
    asm("cvt.rn.f16x2.f32 %0, %1, %2;" : "=r"(r) : "f"(hi), "f"(lo));
    return r;
}

// ---------------------------------------------------------------------------
// Pre-round pass: dst[i] = tf32_rna(src[i])
// ---------------------------------------------------------------------------
__global__ void round_tf32(const float* __restrict__ src, float* __restrict__ dst,
                           int n4) {
    int i = blockIdx.x * blockDim.x + threadIdx.x;
    if (i < n4) {
        float4 v = ((const float4*)src)[i];
        ((float4*)dst)[i] = make_float4(
            __uint_as_float(f2tf32(v.x)), __uint_as_float(f2tf32(v.y)),
            __uint_as_float(f2tf32(v.z)), __uint_as_float(f2tf32(v.w)));
    }
}

// ---------------------------------------------------------------------------
// TF32 GEMM (R10 core, known-pass) + fused K/V fp16 epilogue.
// K section (cols 2048..4095) -> kh plane; V -> vh plane; Q -> fp32 C.
// ---------------------------------------------------------------------------
#define GST 36
#define A_BYTES (128 * GST * 4)
#define STAGE_B (2 * A_BYTES)
#define GEMM_SMEM3 (3 * STAGE_B)
#define RCHUNK (32 * GST * 4)

__device__ __forceinline__ void mma_tf32(float* d, const u32* a, const u32* b) {
    asm volatile(
        "mma.sync.aligned.m16n8k8.row.col.f32.tf32.tf32.f32 "
        "{%0,%1,%2,%3}, {%4,%5,%6,%7}, {%8,%9}, {%0,%1,%2,%3};"
        : "+f"(d[0]), "+f"(d[1]), "+f"(d[2]), "+f"(d[3])
        : "r"(a[0]), "r"(a[1]), "r"(a[2]), "r"(a[3]), "r"(b[0]), "r"(b[1]));
}

__device__ __forceinline__ void ldmx4(u32* r, u32 addr) {
    asm volatile("ldmatrix.sync.aligned.m8n8.x4.shared.b16 {%0,%1,%2,%3}, [%4];"
                 : "=r"(r[0]), "=r"(r[1]), "=r"(r[2]), "=r"(r[3]) : "r"(addr));
}

__device__ __forceinline__ void cp16(u32 dst, const void* src) {
    asm volatile("cp.async.cg.shared.global [%0], [%1], 16;"
                 :: "r"(dst), "l"(src) : "memory");
}

__global__ __launch_bounds__(256, 2)
void gemm_nt_tf32p(const float* __restrict__ A, const float* __restrict__ B,
                   float* __restrict__ C, int M, int N, int K,
                   u32* __restrict__ kh, u32* __restrict__ vh, int qkv_mode) {
    extern __shared__ char sm3[];
    const u32 sbase = smem_u32(sm3);
    const int tid = threadIdx.x;
    const int warp = tid >> 5, lane = tid & 31;
    const int wm = warp >> 1, wn = warp & 1;
    const int fr = lane >> 2, fc = lane & 3;
    const int row0 = blockIdx.y * 128, col0 = blockIdx.x * 128;

    const int lrow = tid >> 3, lcc = tid & 7;
    const u32 so0 = (u32)(lrow * GST + lcc * 4) * 4;
    const float* ga0 = A + (size_t)(row0 + lrow) * K + lcc * 4;
    const float* gb0 = B + (size_t)(col0 + lrow) * K + lcc * 4;
    const size_t rstep = (size_t)32 * K;

    const int gl = lane >> 3, lr8 = lane & 7;
    const u32 afrag = (u32)((wm * 32 + (gl & 1) * 8 + lr8) * GST + (gl >> 1) * 4) * 4;
    const u32 bfrag = A_BYTES +
        (u32)((wn * 64 + (gl >> 1) * 8 + lr8) * GST + (gl & 1) * 4) * 4;

    float acc[2][8][4];
#pragma unroll
    for (int mf = 0; mf < 2; mf++)
#pragma unroll
        for (int g = 0; g < 8; g++)
#pragma unroll
            for (int i = 0; i < 4; i++) acc[mf][g][i] = 0.f;

    const int nslabs = K / 32;

#define ISSUE(slab)                                                          \
    {                                                                        \
        const int st_ = (slab) % 3;                                          \
        const int k0_ = (slab) * 32;                                         \
        const u32 sb_ = sbase + st_ * STAGE_B;                               \
        _Pragma("unroll")                                                    \
        for (int s_ = 0; s_ < 4; s_++) {                                     \
            cp16(sb_ + so0 + RCHUNK * s_, ga0 + rstep * s_ + k0_);           \
            cp16(sb_ + A_BYTES + so0 + RCHUNK * s_, gb0 + rstep * s_ + k0_); \
        }                                                                    \
        asm volatile("cp.async.commit_group;" ::: "memory");                 \
    }

    ISSUE(0);
    ISSUE(1);

#pragma unroll 1
    for (int c = 0; c < nslabs; c++) {
        if (c + 1 < nslabs)
            asm volatile("cp.async.wait_group 1;" ::: "memory");
        else
            asm volatile("cp.async.wait_group 0;" ::: "memory");
        __syncthreads();
        if (c + 2 < nslabs) ISSUE(c + 2);

        const u32 sb = sbase + (c % 3) * STAGE_B;
#pragma unroll
        for (int ks = 0; ks < 32; ks += 8) {
            u32 a[2][4], b[8][2];
            ldmx4(a[0], sb + afrag + ks * 4);
            ldmx4(a[1], sb + afrag + 16 * GST * 4 + ks * 4);
#pragma unroll
            for (int j = 0; j < 4; j++) {
                u32 r[4];
                ldmx4(r, sb + bfrag + j * 16 * GST * 4 + ks * 4);
                b[2 * j][0] = r[0]; b[2 * j][1] = r[1];
                b[2 * j + 1][0] = r[2]; b[2 * j + 1][1] = r[3];
            }
#pragma unroll
            for (int mf = 0; mf < 2; mf++)
#pragma unroll
                for (int g = 0; g < 8; g++)
                    mma_tf32(acc[mf][g], a[mf], b[g]);
        }
    }

    // Epilogue
    if (qkv_mode && col0 >= 2048) {
        const int sec = col0 >> 11;                 // 1=K, 2=V
        u32* __restrict__ ph = (sec == 1) ? kh : vh;
        const int h = (col0 >> 7) & 15;
#pragma unroll
        for (int mf = 0; mf < 2; mf++) {
#pragma unroll
            for (int g = 0; g < 8; g++) {
                int rr = row0 + wm * 32 + mf * 16 + fr;
                int cc = col0 + wn * 64 + g * 8 + 2 * fc;
                int cu = (cc & 127) >> 1;
#pragma unroll
                for (int half = 0; half < 2; half++) {
                    int r2 = rr + half * 8;
                    int bb = r2 >> 11, tok = r2 & 2047;
                    size_t base = ((size_t)(bb * 16 + h) * 2048 + tok) * 64 + cu;
                    ph[base] = packf16(acc[mf][g][half * 2],
                                       acc[mf][g][half * 2 + 1]);
                }
            }
        }
    } else {
#pragma unroll
        for (int mf = 0; mf < 2; mf++) {
#pragma unroll
            for (int g = 0; g < 8; g++) {
                int rr = row0 + wm * 32 + mf * 16 + fr;
                int cc = col0 + wn * 64 + g * 8 + 2 * fc;
                *(float2*)(C + (size_t)rr * N + cc) =
                    make_float2(acc[mf][g][0], acc[mf][g][1]);
                *(float2*)(C + (size_t)(rr + 8) * N + cc) =
                    make_float2(acc[mf][g][2], acc[mf][g][3]);
            }
        }
    }
#undef ISSUE
}

// ===========================================================================
// Flash attention v9 = R14 structure, plain fp16 (no splits):
// QK: single fp16 mma. PV: single fp16 mma.
// 256 thr, 8 warps x 16 q-rows, kv chunk 64, 2-stage cp.async, 2 planes.
// ===========================================================================
#define APL 16384                      // bytes per plane per stage
#define ASTAGE (2 * APL)               // 32768
#define ABIAS_OFF (2 * ASTAGE)         // 65536
#define ATTN_SMEM (2 * ASTAGE + 2048 * 4)   // 73728

__device__ __forceinline__ void mma_f16(float* c, const u32* a, const u32* b) {
    asm volatile(
        "mma.sync.aligned.m16n8k16.row.col.f32.f16.f16.f32 "
        "{%0,%1,%2,%3}, {%4,%5,%6,%7}, {%8,%9}, {%0,%1,%2,%3};"
        : "+f"(c[0]), "+f"(c[1]), "+f"(c[2]), "+f"(c[3])
        : "r"(a[0]), "r"(a[1]), "r"(a[2]), "r"(a[3]), "r"(b[0]), "r"(b[1]));
}

__device__ __forceinline__ void ldsm_x2(u32& r0, u32& r1, u32 addr) {
    asm volatile("ldmatrix.sync.aligned.m8n8.x2.shared.b16 {%0,%1}, [%2];"
                 : "=r"(r0), "=r"(r1) : "r"(addr));
}

__device__ __forceinline__ void ldsm_x2_t(u32& r0, u32& r1, u32 addr) {
    asm volatile("ldmatrix.sync.aligned.m8n8.x2.trans.shared.b16 {%0,%1}, [%2];"
                 : "=r"(r0), "=r"(r1) : "r"(addr));
}

__device__ __forceinline__ float exp2_fast(float t) {
    t = fmaxf(t, -126.f);
    float k = rintf(t);
    float f = t - k;
    float u = f * 0.69314718056f;
    float p = 0.0013888889f;
    p = fmaf(p, u, 0.008333334f);
    p = fmaf(p, u, 0.041666668f);
    p = fmaf(p, u, 0.16666667f);
    p = fmaf(p, u, 0.5f);
    p = fmaf(p, u, 1.0f);
    p = fmaf(p, u, 1.0f);
    return __int_as_float(((int)k + 127) << 23) * p;
}

__global__ __launch_bounds__(256)
void attn_mma(const float* __restrict__ qkv, const int* __restrict__ mask,
              const u32* __restrict__ kh, const u32* __restrict__ vh,
              float* __restrict__ y) {
    extern __shared__ char smA[];
    const u32 sbase = smem_u32(smA);
    float* biasS = (float*)(smA + ABIAS_OFF);

    const int tid = threadIdx.x;
    const int warp = tid >> 5, lane = tid & 31;
    const int fr = lane >> 2, fc = lane & 3;
    const int qt = blockIdx.x;          // 0..15
    const int bh = blockIdx.y;          // 0..63
    const int b = bh >> 4, h = bh & 15;

    const float C = 0.12751743f;        // (1/sqrt(128)) * log2(e)

    const size_t pbase = (size_t)bh * 2048 * 256;
    const char* pkh = (const char*)kh + pbase;
    const char* pvh = (const char*)vh + pbase;

    {
        const int* mg = mask + b * TT;
        for (int t = tid; t < TT; t += 256)
            biasS[t] = mg[t] ? 0.f : -1e30f;
    }

    // ---- Q fragments (single fp16) from fp32 Q section ----
    u32 Qh[8][4];
    {
        const float* Qg = qkv + (size_t)(b * TT + qt * 128 + warp * 16) * (3 * DD)
                        + h * HDIM;
#pragma unroll
        for (int kf = 0; kf < 8; kf++) {
            const float* p0 = Qg + (size_t)fr * (3 * DD) + kf * 16 + 2 * fc;
            const float* p1 = p0 + (size_t)8 * (3 * DD);
            float2 v0 = *(const float2*)p0;
            float2 v1 = *(const float2*)p1;
            float2 v2 = *(const float2*)(p0 + 8);
            float2 v3 = *(const float2*)(p1 + 8);
            Qh[kf][0] = packf16(v0.x, v0.y);
            Qh[kf][1] = packf16(v1.x, v1.y);
            Qh[kf][2] = packf16(v2.x, v2.y);
            Qh[kf][3] = packf16(v3.x, v3.y);
        }
    }

    float o[16][4];
#pragma unroll
    for (int n = 0; n < 16; n++)
#pragma unroll
        for (int j = 0; j < 4; j++) o[n][j] = 0.f;
    float m0 = -1e30f, m1 = -1e30f, l0 = 0.f, l1 = 0.f;

#define AISSUE(ktc)                                                            \
    {                                                                          \
        const u32 sb_ = sbase + ((ktc) & 1) * ASTAGE;                          \
        const size_t go_ = (size_t)(ktc) * 16384;                              \
        _Pragma("unroll")                                                      \
        for (int i_ = 0; i_ < 8; i_++) {                                       \
            int cid_ = tid + (i_ & 3) * 256;                                   \
            int row_ = cid_ >> 4, c_ = cid_ & 15;                              \
            const char* p_ = (i_ >> 2) == 0 ? pkh : pvh;                       \
            u32 d_ = sb_ + (u32)(i_ >> 2) * APL + row_ * 256 +                 \
                     (((u32)(c_ ^ (row_ & 7))) << 4);                          \
            cp16(d_, p_ + go_ + row_ * 256 + c_ * 16);                         \
        }                                                                      \
        asm volatile("cp.async.commit_group;" ::: "memory");                   \
    }

    AISSUE(0);

    const int lrow8 = lane & 7;
    const int lsel = (lane >> 3) & 1;
    const int lrow16 = lane & 15;

#define KOFF(kf_, n_) \
    ((u32)(((n_) * 8 + lrow8) * 256) + ((u32)(((kf_) * 2 + lsel) ^ lrow8) << 4))
#define VOFF(n_, kf_) \
    ((u32)(((kf_) * 16 + lrow16) * 256) + ((u32)((n_) ^ (lrow16 & 7)) << 4))

#pragma unroll 1
    for (int kt = 0; kt < TT / 64; kt++) {
        asm volatile("cp.async.wait_group 0;" ::: "memory");
        __syncthreads();
        if (kt + 1 < TT / 64) AISSUE(kt + 1);

        const u32 sb = sbase + (kt & 1) * ASTAGE;

        // ---- S = Q K^T (single fp16 mma), K fragments double-buffered ----
        float s[8][4];
#pragma unroll
        for (int n = 0; n < 8; n++)
#pragma unroll
            for (int j = 0; j < 4; j++) s[n][j] = 0.f;

        {
            u32 bhf[2][2];
            u32 off0 = KOFF(0, 0);
            ldsm_x2(bhf[0][0], bhf[0][1], sb + off0);
#pragma unroll
            for (int idx = 0; idx < 64; idx++) {
                const int kf = idx >> 3, n = idx & 7;
                const int cur = idx & 1, nxt = cur ^ 1;
                if (idx < 63) {
                    const int i2 = idx + 1;
                    u32 off = KOFF(i2 >> 3, i2 & 7);
                    ldsm_x2(bhf[nxt][0], bhf[nxt][1], sb + off);
                }
                mma_f16(s[n], Qh[kf], bhf[cur]);
            }
        }

        // ---- online softmax (log2 domain) ----
        const float* brow = biasS + kt * 64;
        float mx0 = -1e30f, mx1 = -1e30f;
#pragma unroll
        for (int n = 0; n < 8; n++) {
            float2 bb = *(const float2*)&brow[n * 8 + 2 * fc];
            s[n][0] = fmaf(s[n][0], C, bb.x);
            s[n][1] = fmaf(s[n][1], C, bb.y);
            s[n][2] = fmaf(s[n][2], C, bb.x);
            s[n][3] = fmaf(s[n][3], C, bb.y);
            mx0 = fmaxf(mx0, fmaxf(s[n][0], s[n][1]));
            mx1 = fmaxf(mx1, fmaxf(s[n][2], s[n][3]));
        }
        mx0 = fmaxf(mx0, __shfl_xor_sync(0xffffffffu, mx0, 1));
        mx0 = fmaxf(mx0, __shfl_xor_sync(0xffffffffu, mx0, 2));
        mx1 = fmaxf(mx1, __shfl_xor_sync(0xffffffffu, mx1, 1));
        mx1 = fmaxf(mx1, __shfl_xor_sync(0xffffffffu, mx1, 2));

        float m0n = fmaxf(m0, mx0), m1n = fmaxf(m1, mx1);
        float f0 = exp2_fast(m0 - m0n), f1 = exp2_fast(m1 - m1n);
        m0 = m0n; m1 = m1n;

        float sum0 = 0.f, sum1 = 0.f;
#pragma unroll
        for (int n = 0; n < 8; n++) {
            s[n][0] = exp2_fast(s[n][0] - m0n);
            s[n][1] = exp2_fast(s[n][1] - m0n);
            s[n][2] = exp2_fast(s[n][2] - m1n);
            s[n][3] = exp2_fast(s[n][3] - m1n);
            sum0 += s[n][0] + s[n][1];
            sum1 += s[n][2] + s[n][3];
        }
        sum0 += __shfl_xor_sync(0xffffffffu, sum0, 1);
        sum0 += __shfl_xor_sync(0xffffffffu, sum0, 2);
        sum1 += __shfl_xor_sync(0xffffffffu, sum1, 1);
        sum1 += __shfl_xor_sync(0xffffffffu, sum1, 2);
        l0 = l0 * f0 + sum0;
        l1 = l1 * f1 + sum1;

#pragma unroll
        for (int n = 0; n < 16; n++) {
            o[n][0] *= f0; o[n][1] *= f0;
            o[n][2] *= f1; o[n][3] *= f1;
        }

        // pack P -> single fp16 A fragments
        u32 pa[4][4];
#pragma unroll
        for (int kf = 0; kf < 4; kf++) {
            pa[kf][0] = packf16(s[2 * kf][0], s[2 * kf][1]);
            pa[kf][1] = packf16(s[2 * kf][2], s[2 * kf][3]);
            pa[kf][2] = packf16(s[2 * kf + 1][0], s[2 * kf + 1][1]);
            pa[kf][3] = packf16(s[2 * kf + 1][2], s[2 * kf + 1][3]);
        }

        // ---- O += P V (single fp16 mma), V fragments double-buffered ----
        {
            u32 bv[2][2];
            u32 off0 = VOFF(0, 0);
            ldsm_x2_t(bv[0][0], bv[0][1], sb + APL + off0);
#pragma unroll
            for (int idx = 0; idx < 64; idx++) {
                const int n = idx >> 2, kf = idx & 3;
                const int cur = idx & 1, nxt = cur ^ 1;
                if (idx < 63) {
                    const int i2 = idx + 1;
                    u32 off = VOFF(i2 >> 2, i2 & 3);
                    ldsm_x2_t(bv[nxt][0], bv[nxt][1], sb + APL + off);
                }
                mma_f16(o[n], pa[kf], bv[cur]);
            }
        }
    }
#undef AISSUE
#undef KOFF
#undef VOFF

    // ---- normalize and store (tf32-rounded) ----
    float inv0 = 1.f / l0, inv1 = 1.f / l1;
    {
        size_t r0 = (size_t)(b * TT + qt * 128 + warp * 16 + fr) * DD + h * HDIM;
        size_t r1 = r0 + (size_t)8 * DD;
#pragma unroll
        for (int n = 0; n < 16; n++) {
            int cc = n * 8 + 2 * fc;
            *(float2*)(y + r0 + cc) = make_float2(
                __uint_as_float(f2tf32(o[n][0] * inv0)),
                __uint_as_float(f2tf32(o[n][1] * inv0)));
            *(float2*)(y + r1 + cc) = make_float2(
                __uint_as_float(f2tf32(o[n][2] * inv1)),
                __uint_as_float(f2tf32(o[n][3] * inv1)));
        }
    }
}

// ---------------------------------------------------------------------------
// Launch
// ---------------------------------------------------------------------------
extern "C" void kernel_launch(void* const* d_in, const int* in_sizes, int n_in,
                              void* d_out, int out_size) {
    const float* x     = (const float*)d_in[0];
    const int*   mask  = (const int*)d_in[1];
    const float* w_qkv = (const float*)d_in[2];
    const float* w_o   = (const float*)d_in[3];
    float* out = (float*)d_out;

    float *qkv, *yb, *xr, *wq, *wo;
    u32 *kh, *vh;
    cudaGetSymbolAddress((void**)&qkv, g_qkv);
    cudaGetSymbolAddress((void**)&yb, g_y);
    cudaGetSymbolAddress((void**)&xr, g_xr);
    cudaGetSymbolAddress((void**)&wq, g_wq);
    cudaGetSymbolAddress((void**)&wo, g_wo);
    cudaGetSymbolAddress((void**)&kh, g_kh);
    cudaGetSymbolAddress((void**)&vh, g_vh);
    cudaFuncSetAttribute(gemm_nt_tf32p, cudaFuncAttributeMaxDynamicSharedMemorySize,
                         GEMM_SMEM3);
    cudaFuncSetAttribute(attn_mma, cudaFuncAttributeMaxDynamicSharedMemorySize,
                         ATTN_SMEM);

    // Pre-round GEMM inputs to tf32
    {
        int n4x = (BB * TT * DD) / 4;
        int n4q = (3 * DD * DD) / 4;
        int n4o = (DD * DD) / 4;
        round_tf32<<<(n4x + 255) / 256, 256>>>(x, xr, n4x);
        round_tf32<<<(n4q + 255) / 256, 256>>>(w_qkv, wq, n4q);
        round_tf32<<<(n4o + 255) / 256, 256>>>(w_o, wo, n4o);
    }

    // QKV = X @ Wqkv^T; K/V sections -> fp16 planes, Q -> fp32 C
    gemm_nt_tf32p<<<dim3(3 * DD / 128, BB * TT / 128), 256, GEMM_SMEM3>>>(
        xr, wq, qkv, BB * TT, 3 * DD, DD, kh, vh, 1);

    // Attention -> y (tf32-rounded)
    attn_mma<<<dim3(TT / 128, BB * HH), 256, ATTN_SMEM>>>(
        qkv, mask, kh, vh, yb);

    // out = Y @ Wo^T
    gemm_nt_tf32p<<<dim3(DD / 128, BB * TT / 128), 256, GEMM_SMEM3>>>(
        yb, wo, out, BB * TT, DD, DD, nullptr, nullptr, 0);
}

// round 17
// speedup vs baseline: 1.9621x; 1.5990x over previous
#include <cuda_runtime.h>
#include <cuda_fp16.h>
#include <cstdint>
#include <math.h>

using u32 = unsigned int;

// Problem constants
#define BB 4
#define TT 2048
#define DD 2048
#define HH 16
#define HDIM 128

// Scratch (allocation-free rule: __device__ globals)
__device__ float g_qkv[(size_t)BB * TT * 3 * DD];   // Q section fp32; K/V unused
// fp16 packed planes (u32 = f16x2)
__device__ u32 g_xh[(size_t)BB * TT * DD / 2];      // x fp16, row-major
__device__ u32 g_wqh[(size_t)3 * DD * DD / 2];      // w_qkv fp16
__device__ u32 g_woh[(size_t)DD * DD / 2];          // w_o fp16
__device__ u32 g_yh[(size_t)BB * TT * DD / 2];      // attention output fp16
// fp16 K/V planes: [(b*16+h)][t][128] half (row = 256B), as u32
__device__ u32 g_kh[(size_t)64 * 2048 * 64];
__device__ u32 g_vh[(size_t)64 * 2048 * 64];

__device__ __forceinline__ u32 smem_u32(const void* p) {
    u32 a;
    asm("{ .reg .u64 t; cvta.to.shared.u64 t, %1; cvt.u32.u64 %0, t; }"
        : "=r"(a) : "l"(p));
    return a;
}

// pack two fp32 into f16x2 (first arg in low half)
__device__ __forceinline__ u32 packf16(float lo, float hi) {
    u32 r;
    asm("cvt.rn.f16x2.f32 %0, %1, %2;" : "=r"(r) : "f"(hi), "f"(lo));
    return r;
}

// ---------------------------------------------------------------------------
// Pack pass: fp32 pairs -> f16x2
// ---------------------------------------------------------------------------
__global__ void pack_f16(const float* __restrict__ src, u32* __restrict__ dst,
                         int n2) {
    int i = blockIdx.x * blockDim.x + threadIdx.x;
    if (i < n2) {
        float2 v = ((const float2*)src)[i];
        dst[i] = packf16(v.x, v.y);
    }
}

// ---------------------------------------------------------------------------
// FP16 tensor-core GEMM: C[M,N] = A[M,K] @ B[N,K]^T, fp16 operand planes.
// CTA 128x128, warp 32x64 (8 warps 4x2), BK=64 halves, 3-stage cp.async,
// XOR-swizzled 128B rows, mma.m16n8k16.f16.
// qkv_mode: Q section -> fp32 C; K section -> kh plane; V -> vh plane.
// ---------------------------------------------------------------------------
#define HPL 16384                    // bytes per matrix tile (128 rows x 128B)
#define HSTG (2 * HPL)               // 32768
#define HSMEM (3 * HSTG)             // 98304

__device__ __forceinline__ void mma_f16(float* c, const u32* a, const u32* b) {
    asm volatile(
        "mma.sync.aligned.m16n8k16.row.col.f32.f16.f16.f32 "
        "{%0,%1,%2,%3}, {%4,%5,%6,%7}, {%8,%9}, {%0,%1,%2,%3};"
        : "+f"(c[0]), "+f"(c[1]), "+f"(c[2]), "+f"(c[3])
        : "r"(a[0]), "r"(a[1]), "r"(a[2]), "r"(a[3]), "r"(b[0]), "r"(b[1]));
}

__device__ __forceinline__ void ldmx4(u32* r, u32 addr) {
    asm volatile("ldmatrix.sync.aligned.m8n8.x4.shared.b16 {%0,%1,%2,%3}, [%4];"
                 : "=r"(r[0]), "=r"(r[1]), "=r"(r[2]), "=r"(r[3]) : "r"(addr));
}

__device__ __forceinline__ void ldsm_x2(u32& r0, u32& r1, u32 addr) {
    asm volatile("ldmatrix.sync.aligned.m8n8.x2.shared.b16 {%0,%1}, [%2];"
                 : "=r"(r0), "=r"(r1) : "r"(addr));
}

__device__ __forceinline__ void ldsm_x2_t(u32& r0, u32& r1, u32 addr) {
    asm volatile("ldmatrix.sync.aligned.m8n8.x2.trans.shared.b16 {%0,%1}, [%2];"
                 : "=r"(r0), "=r"(r1) : "r"(addr));
}

__device__ __forceinline__ void cp16(u32 dst, const void* src) {
    asm volatile("cp.async.cg.shared.global [%0], [%1], 16;"
                 :: "r"(dst), "l"(src) : "memory");
}

__global__ __launch_bounds__(256, 2)
void gemm_f16p(const u32* __restrict__ Ah, const u32* __restrict__ Bh,
               float* __restrict__ C, int M, int N, int K,
               u32* __restrict__ kh, u32* __restrict__ vh, int qkv_mode) {
    extern __shared__ char smG[];
    const u32 sbase = smem_u32(smG);
    const int tid = threadIdx.x;
    const int warp = tid >> 5, lane = tid & 31;
    const int wm = warp >> 1, wn = warp & 1;
    const int fr = lane >> 2, fc = lane & 3;
    const int row0 = blockIdx.y * 128, col0 = blockIdx.x * 128;
    const size_t Kb = (size_t)K * 2;            // bytes per gmem plane row

    // fragment addressing (validated patterns: R8 A-map, attention B-map)
    const int lr8 = lane & 7, gl = lane >> 3;
    const u32 arow = (u32)(wm * 32 + (gl & 1) * 8 + lr8);
    const int acb = gl >> 1;                    // A chunk base 0/1
    const u32 abase = arow * 128;
    const u32 ax = arow & 7;
    const int lsel = (lane >> 3) & 1;           // B k-half select (lanes 0-15)
    const u32 bbase = HPL + (u32)(wn * 64 + lr8) * 128;
    const u32 bx = (u32)lr8;

    float acc[2][8][4];
#pragma unroll
    for (int mf = 0; mf < 2; mf++)
#pragma unroll
        for (int g = 0; g < 8; g++)
#pragma unroll
            for (int i = 0; i < 4; i++) acc[mf][g][i] = 0.f;

    const int nslabs = K / 64;

#define ISSUE(slab)                                                           \
    {                                                                         \
        const int st_ = (slab) % 3;                                           \
        const size_t kb_ = (size_t)(slab) * 128;  /* 64 halves = 128 bytes */ \
        const u32 sb_ = sbase + st_ * HSTG;                                   \
        _Pragma("unroll")                                                     \
        for (int it_ = 0; it_ < 4; it_++) {                                   \
            int cid_ = tid + it_ * 256;                                       \
            int row_ = cid_ >> 3, c_ = cid_ & 7;                              \
            u32 sw_ = ((u32)(c_ ^ (row_ & 7))) << 4;                          \
            cp16(sb_ + row_ * 128 + sw_,                                      \
                 (const char*)Ah + (size_t)(row0 + row_) * Kb + kb_ + c_ * 16); \
            cp16(sb_ + HPL + row_ * 128 + sw_,                                \
                 (const char*)Bh + (size_t)(col0 + row_) * Kb + kb_ + c_ * 16); \
        }                                                                     \
        asm volatile("cp.async.commit_group;" ::: "memory");                  \
    }

    ISSUE(0);
    ISSUE(1);

#pragma unroll 1
    for (int c = 0; c < nslabs; c++) {
        if (c + 1 < nslabs)
            asm volatile("cp.async.wait_group 1;" ::: "memory");
        else
            asm volatile("cp.async.wait_group 0;" ::: "memory");
        __syncthreads();
        if (c + 2 < nslabs) ISSUE(c + 2);

        const u32 sb = sbase + (c % 3) * HSTG;
#pragma unroll
        for (int ks = 0; ks < 4; ks++) {
            u32 a[2][4], b[8][2];
            u32 axor = (((u32)(ks * 2 + acb)) ^ ax) << 4;
            ldmx4(a[0], sb + abase + axor);
            ldmx4(a[1], sb + abase + 2048 + axor);   // +16 rows
            u32 bxor = (((u32)(ks * 2 + lsel)) ^ bx) << 4;
#pragma unroll
            for (int j = 0; j < 8; j++)
                ldsm_x2(b[j][0], b[j][1], sb + bbase + j * 1024 + bxor);
#pragma unroll
            for (int mf = 0; mf < 2; mf++)
#pragma unroll
                for (int g = 0; g < 8; g++)
                    mma_f16(acc[mf][g], a[mf], b[g]);
        }
    }

    // Epilogue
    if (qkv_mode && col0 >= 2048) {
        const int sec = col0 >> 11;                 // 1=K, 2=V
        u32* __restrict__ ph = (sec == 1) ? kh : vh;
        const int h = (col0 >> 7) & 15;
#pragma unroll
        for (int mf = 0; mf < 2; mf++) {
#pragma unroll
            for (int g = 0; g < 8; g++) {
                int rr = row0 + wm * 32 + mf * 16 + fr;
                int cc = col0 + wn * 64 + g * 8 + 2 * fc;
                int cu = (cc & 127) >> 1;
#pragma unroll
                for (int half = 0; half < 2; half++) {
                    int r2 = rr + half * 8;
                    int bb = r2 >> 11, tok = r2 & 2047;
                    size_t base = ((size_t)(bb * 16 + h) * 2048 + tok) * 64 + cu;
                    ph[base] = packf16(acc[mf][g][half * 2],
                                       acc[mf][g][half * 2 + 1]);
                }
            }
        }
    } else {
#pragma unroll
        for (int mf = 0; mf < 2; mf++) {
#pragma unroll
            for (int g = 0; g < 8; g++) {
                int rr = row0 + wm * 32 + mf * 16 + fr;
                int cc = col0 + wn * 64 + g * 8 + 2 * fc;
                *(float2*)(C + (size_t)rr * N + cc) =
                    make_float2(acc[mf][g][0], acc[mf][g][1]);
                *(float2*)(C + (size_t)(rr + 8) * N + cc) =
                    make_float2(acc[mf][g][2], acc[mf][g][3]);
            }
        }
    }
#undef ISSUE
}

// ===========================================================================
// Flash attention (R16 structure, known-pass): plain fp16 QK and PV.
// Output stored as packed f16x2 plane (consumed natively by the Wo GEMM).
// ===========================================================================
#define APL 16384                      // bytes per plane per stage
#define ASTAGE (2 * APL)               // 32768
#define ABIAS_OFF (2 * ASTAGE)         // 65536
#define ATTN_SMEM (2 * ASTAGE + 2048 * 4)   // 73728

__device__ __forceinline__ float exp2_fast(float t) {
    t = fmaxf(t, -126.f);
    float k = rintf(t);
    float f = t - k;
    float u = f * 0.69314718056f;
    float p = 0.0013888889f;
    p = fmaf(p, u, 0.008333334f);
    p = fmaf(p, u, 0.041666668f);
    p = fmaf(p, u, 0.16666667f);
    p = fmaf(p, u, 0.5f);
    p = fmaf(p, u, 1.0f);
    p = fmaf(p, u, 1.0f);
    return __int_as_float(((int)k + 127) << 23) * p;
}

__global__ __launch_bounds__(256)
void attn_mma(const float* __restrict__ qkv, const int* __restrict__ mask,
              const u32* __restrict__ kh, const u32* __restrict__ vh,
              u32* __restrict__ yh) {
    extern __shared__ char smA[];
    const u32 sbase = smem_u32(smA);
    float* biasS = (float*)(smA + ABIAS_OFF);

    const int tid = threadIdx.x;
    const int warp = tid >> 5, lane = tid & 31;
    const int fr = lane >> 2, fc = lane & 3;
    const int qt = blockIdx.x;          // 0..15
    const int bh = blockIdx.y;          // 0..63
    const int b = bh >> 4, h = bh & 15;

    const float C = 0.12751743f;        // (1/sqrt(128)) * log2(e)

    const size_t pbase = (size_t)bh * 2048 * 256;
    const char* pkh = (const char*)kh + pbase;
    const char* pvh = (const char*)vh + pbase;

    {
        const int* mg = mask + b * TT;
        for (int t = tid; t < TT; t += 256)
            biasS[t] = mg[t] ? 0.f : -1e30f;
    }

    // ---- Q fragments (single fp16) from fp32 Q section ----
    u32 Qh[8][4];
    {
        const float* Qg = qkv + (size_t)(b * TT + qt * 128 + warp * 16) * (3 * DD)
                        + h * HDIM;
#pragma unroll
        for (int kf = 0; kf < 8; kf++) {
            const float* p0 = Qg + (size_t)fr * (3 * DD) + kf * 16 + 2 * fc;
            const float* p1 = p0 + (size_t)8 * (3 * DD);
            float2 v0 = *(const float2*)p0;
            float2 v1 = *(const float2*)p1;
            float2 v2 = *(const float2*)(p0 + 8);
            float2 v3 = *(const float2*)(p1 + 8);
            Qh[kf][0] = packf16(v0.x, v0.y);
            Qh[kf][1] = packf16(v1.x, v1.y);
            Qh[kf][2] = packf16(v2.x, v2.y);
            Qh[kf][3] = packf16(v3.x, v3.y);
        }
    }

    float o[16][4];
#pragma unroll
    for (int n = 0; n < 16; n++)
#pragma unroll
        for (int j = 0; j < 4; j++) o[n][j] = 0.f;
    float m0 = -1e30f, m1 = -1e30f, l0 = 0.f, l1 = 0.f;

#define AISSUE(ktc)                                                            \
    {                                                                          \
        const u32 sb_ = sbase + ((ktc) & 1) * ASTAGE;                          \
        const size_t go_ = (size_t)(ktc) * 16384;                              \
        _Pragma("unroll")                                                      \
        for (int i_ = 0; i_ < 8; i_++) {                                       \
            int cid_ = tid + (i_ & 3) * 256;                                   \
            int row_ = cid_ >> 4, c_ = cid_ & 15;                              \
            const char* p_ = (i_ >> 2) == 0 ? pkh : pvh;                       \
            u32 d_ = sb_ + (u32)(i_ >> 2) * APL + row_ * 256 +                 \
                     (((u32)(c_ ^ (row_ & 7))) << 4);                          \
            cp16(d_, p_ + go_ + row_ * 256 + c_ * 16);                         \
        }                                                                      \
        asm volatile("cp.async.commit_group;" ::: "memory");                   \
    }

    AISSUE(0);

    const int lrow8 = lane & 7;
    const int lsel = (lane >> 3) & 1;
    const int lrow16 = lane & 15;

#define KOFF(kf_, n_) \
    ((u32)(((n_) * 8 + lrow8) * 256) + ((u32)(((kf_) * 2 + lsel) ^ lrow8) << 4))
#define VOFF(n_, kf_) \
    ((u32)(((kf_) * 16 + lrow16) * 256) + ((u32)((n_) ^ (lrow16 & 7)) << 4))

#pragma unroll 1
    for (int kt = 0; kt < TT / 64; kt++) {
        asm volatile("cp.async.wait_group 0;" ::: "memory");
        __syncthreads();
        if (kt + 1 < TT / 64) AISSUE(kt + 1);

        const u32 sb = sbase + (kt & 1) * ASTAGE;

        // ---- S = Q K^T (single fp16 mma), K fragments double-buffered ----
        float s[8][4];
#pragma unroll
        for (int n = 0; n < 8; n++)
#pragma unroll
            for (int j = 0; j < 4; j++) s[n][j] = 0.f;

        {
            u32 bhf[2][2];
            u32 off0 = KOFF(0, 0);
            ldsm_x2(bhf[0][0], bhf[0][1], sb + off0);
#pragma unroll
            for (int idx = 0; idx < 64; idx++) {
                const int kf = idx >> 3, n = idx & 7;
                const int cur = idx & 1, nxt = cur ^ 1;
                if (idx < 63) {
                    const int i2 = idx + 1;
                    u32 off = KOFF(i2 >> 3, i2 & 7);
                    ldsm_x2(bhf[nxt][0], bhf[nxt][1], sb + off);
                }
                mma_f16(s[n], Qh[kf], bhf[cur]);
            }
        }

        // ---- online softmax (log2 domain) ----
        const float* brow = biasS + kt * 64;
        float mx0 = -1e30f, mx1 = -1e30f;
#pragma unroll
        for (int n = 0; n < 8; n++) {
            float2 bb = *(const float2*)&brow[n * 8 + 2 * fc];
            s[n][0] = fmaf(s[n][0], C, bb.x);
            s[n][1] = fmaf(s[n][1], C, bb.y);
            s[n][2] = fmaf(s[n][2], C, bb.x);
            s[n][3] = fmaf(s[n][3], C, bb.y);
            mx0 = fmaxf(mx0, fmaxf(s[n][0], s[n][1]));
            mx1 = fmaxf(mx1, fmaxf(s[n][2], s[n][3]));
        }
        mx0 = fmaxf(mx0, __shfl_xor_sync(0xffffffffu, mx0, 1));
        mx0 = fmaxf(mx0, __shfl_xor_sync(0xffffffffu, mx0, 2));
        mx1 = fmaxf(mx1, __shfl_xor_sync(0xffffffffu, mx1, 1));
        mx1 = fmaxf(mx1, __shfl_xor_sync(0xffffffffu, mx1, 2));

        float m0n = fmaxf(m0, mx0), m1n = fmaxf(m1, mx1);
        float f0 = exp2_fast(m0 - m0n), f1 = exp2_fast(m1 - m1n);
        m0 = m0n; m1 = m1n;

        float sum0 = 0.f, sum1 = 0.f;
#pragma unroll
        for (int n = 0; n < 8; n++) {
            s[n][0] = exp2_fast(s[n][0] - m0n);
            s[n][1] = exp2_fast(s[n][1] - m0n);
            s[n][2] = exp2_fast(s[n][2] - m1n);
            s[n][3] = exp2_fast(s[n][3] - m1n);
            sum0 += s[n][0] + s[n][1];
            sum1 += s[n][2] + s[n][3];
        }
        sum0 += __shfl_xor_sync(0xffffffffu, sum0, 1);
        sum0 += __shfl_xor_sync(0xffffffffu, sum0, 2);
        sum1 += __shfl_xor_sync(0xffffffffu, sum1, 1);
        sum1 += __shfl_xor_sync(0xffffffffu, sum1, 2);
        l0 = l0 * f0 + sum0;
        l1 = l1 * f1 + sum1;

#pragma unroll
        for (int n = 0; n < 16; n++) {
            o[n][0] *= f0; o[n][1] *= f0;
            o[n][2] *= f1; o[n][3] *= f1;
        }

        // pack P -> single fp16 A fragments
        u32 pa[4][4];
#pragma unroll
        for (int kf = 0; kf < 4; kf++) {
            pa[kf][0] = packf16(s[2 * kf][0], s[2 * kf][1]);
            pa[kf][1] = packf16(s[2 * kf][2], s[2 * kf][3]);
            pa[kf][2] = packf16(s[2 * kf + 1][0], s[2 * kf + 1][1]);
            pa[kf][3] = packf16(s[2 * kf + 1][2], s[2 * kf + 1][3]);
        }

        // ---- O += P V (single fp16 mma), V fragments double-buffered ----
        {
            u32 bv[2][2];
            u32 off0 = VOFF(0, 0);
            ldsm_x2_t(bv[0][0], bv[0][1], sb + APL + off0);
#pragma unroll
            for (int idx = 0; idx < 64; idx++) {
                const int n = idx >> 2, kf = idx & 3;
                const int cur = idx & 1, nxt = cur ^ 1;
                if (idx < 63) {
                    const int i2 = idx + 1;
                    u32 off = VOFF(i2 >> 2, i2 & 3);
                    ldsm_x2_t(bv[nxt][0], bv[nxt][1], sb + APL + off);
                }
                mma_f16(o[n], pa[kf], bv[cur]);
            }
        }
    }
#undef AISSUE
#undef KOFF
#undef VOFF

    // ---- normalize and store as fp16 plane (consumed by Wo GEMM) ----
    float inv0 = 1.f / l0, inv1 = 1.f / l1;
    {
        size_t r0 = (size_t)(b * TT + qt * 128 + warp * 16 + fr) * DD + h * HDIM;
        size_t r1 = r0 + (size_t)8 * DD;
#pragma unroll
        for (int n = 0; n < 16; n++) {
            int cc = n * 8 + 2 * fc;
            yh[(r0 + cc) >> 1] = packf16(o[n][0] * inv0, o[n][1] * inv0);
            yh[(r1 + cc) >> 1] = packf16(o[n][2] * inv1, o[n][3] * inv1);
        }
    }
}

// ---------------------------------------------------------------------------
// Launch
// ---------------------------------------------------------------------------
extern "C" void kernel_launch(void* const* d_in, const int* in_sizes, int n_in,
                              void* d_out, int out_size) {
    const float* x     = (const float*)d_in[0];
    const int*   mask  = (const int*)d_in[1];
    const float* w_qkv = (const float*)d_in[2];
    const float* w_o   = (const float*)d_in[3];
    float* out = (float*)d_out;

    float* qkv;
    u32 *xh, *wqh, *woh, *yh, *kh, *vh;
    cudaGetSymbolAddress((void**)&qkv, g_qkv);
    cudaGetSymbolAddress((void**)&xh, g_xh);
    cudaGetSymbolAddress((void**)&wqh, g_wqh);
    cudaGetSymbolAddress((void**)&woh, g_woh);
    cudaGetSymbolAddress((void**)&yh, g_yh);
    cudaGetSymbolAddress((void**)&kh, g_kh);
    cudaGetSymbolAddress((void**)&vh, g_vh);
    cudaFuncSetAttribute(gemm_f16p, cudaFuncAttributeMaxDynamicSharedMemorySize,
                         HSMEM);
    cudaFuncSetAttribute(attn_mma, cudaFuncAttributeMaxDynamicSharedMemorySize,
                         ATTN_SMEM);

    // Pack GEMM inputs to fp16 planes
    {
        int n2x = (BB * TT * DD) / 2;
        int n2q = (3 * DD * DD) / 2;
        int n2o = (DD * DD) / 2;
        pack_f16<<<(n2x + 255) / 256, 256>>>(x, xh, n2x);
        pack_f16<<<(n2q + 255) / 256, 256>>>(w_qkv, wqh, n2q);
        pack_f16<<<(n2o + 255) / 256, 256>>>(w_o, woh, n2o);
    }

    // QKV = X @ Wqkv^T (fp16 mma); K/V -> fp16 planes, Q -> fp32
    gemm_f16p<<<dim3(3 * DD / 128, BB * TT / 128), 256, HSMEM>>>(
        xh, wqh, qkv, BB * TT, 3 * DD, DD, kh, vh, 1);

    // Attention -> yh (fp16 plane)
    attn_mma<<<dim3(TT / 128, BB * HH), 256, ATTN_SMEM>>>(
        qkv, mask, kh, vh, yh);

    // out = Y @ Wo^T (fp16 mma), fp32 result
    gemm_f16p<<<dim3(DD / 128, BB * TT / 128), 256, HSMEM>>>(
        yh, woh, out, BB * TT, DD, DD, nullptr, nullptr, 0);
}